// round 5
// baseline (speedup 1.0000x reference)
#include <cuda_runtime.h>

#define NN   50000
#define EE   800000
#define NPAD 50048

// ---------------- scratch (device globals; no allocation allowed) -----------
__device__ __align__(16) float g_cnt[NPAD];
__device__ __align__(16) float g_cntinv[NPAD];
__device__ __align__(16) float g_PC[(size_t)NPAD * 256];   // [P | C] fused GEMM output
__device__ __align__(16) float g_S [(size_t)NPAD * 128];   // scatter accumulator
__device__ __align__(16) float g_H [(size_t)NPAD * 128];   // layer activations
__device__ __align__(16) float g_B [128 * 256];            // [Wl | Wr+Ws] current layer
__device__ __align__(16) float g_bias[128];                // bl + bs current layer

// ---------------- small utility kernels -------------------------------------
__global__ void k_zero_cnt() {
    int i = blockIdx.x * blockDim.x + threadIdx.x;
    if (i < NPAD) g_cnt[i] = 0.0f;
}

__global__ void k_zero_S(int n) {
    int i = blockIdx.x * blockDim.x + threadIdx.x;
    if (i < n) g_S[i] = 0.0f;
}

__global__ void k_count(const int* __restrict__ dst) {
    int e = blockIdx.x * blockDim.x + threadIdx.x;
    if (e < EE) atomicAdd(&g_cnt[dst[e]], 1.0f);
}

__global__ void k_inv() {
    int i = blockIdx.x * blockDim.x + threadIdx.x;
    if (i < NN) g_cntinv[i] = 1.0f / fmaxf(g_cnt[i], 1.0f);
}

// Build B = [Wl | Wr+Ws]  (128 x 2*dout) and bias = bl + bs
__global__ void k_buildB(const float* __restrict__ Wl, const float* __restrict__ Wr,
                         const float* __restrict__ Ws, const float* __restrict__ bl,
                         const float* __restrict__ bs, int dout) {
    int i = blockIdx.x * blockDim.x + threadIdx.x;
    int d2 = 2 * dout;
    if (i < 128 * d2) {
        int k = i / d2, j = i % d2;
        g_B[i] = (j < dout) ? Wl[k * dout + j]
                            : (Wr[k * dout + (j - dout)] + Ws[k * dout + (j - dout)]);
    }
    if (i < dout) g_bias[i] = bl[i] + bs[i];
}

// ---------------- SGEMM: C[n,dout2] = A[n,128] @ g_B[128,dout2] -------------
// 64x64 block tile, 16 K-tile, 256 threads, 4x4 micro-tile per thread.
__global__ void __launch_bounds__(256)
k_gemm(const float* __restrict__ Aext, int useH, int nrows, int dout2) {
    const float* __restrict__ A = useH ? g_H : Aext;
    __shared__ float As[16][64];
    __shared__ float Bs[16][64];

    int t  = threadIdx.x;
    int ty = t >> 4, tx = t & 15;
    int row0 = blockIdx.x * 64;
    int col0 = blockIdx.y * 64;

    int la_r = t >> 2;           // A tile row   (0..63)
    int la_c = (t & 3) * 4;      // A tile k-col (0..12 step 4)
    int lb_r = t >> 4;           // B tile k-row (0..15)
    int lb_c = (t & 15) * 4;     // B tile col   (0..60 step 4)

    float acc[4][4];
#pragma unroll
    for (int i = 0; i < 4; i++)
#pragma unroll
        for (int j = 0; j < 4; j++) acc[i][j] = 0.0f;

    for (int k0 = 0; k0 < 128; k0 += 16) {
        // load A 64x16 (transposed into As[k][m])
        float4 av = make_float4(0.f, 0.f, 0.f, 0.f);
        int ar = row0 + la_r;
        if (ar < nrows) av = *(const float4*)(A + (size_t)ar * 128 + k0 + la_c);
        As[la_c + 0][la_r] = av.x;
        As[la_c + 1][la_r] = av.y;
        As[la_c + 2][la_r] = av.z;
        As[la_c + 3][la_r] = av.w;
        // load B 16x64
        float4 bv = *(const float4*)(g_B + (size_t)(k0 + lb_r) * dout2 + col0 + lb_c);
        *(float4*)&Bs[lb_r][lb_c] = bv;
        __syncthreads();

#pragma unroll
        for (int kk = 0; kk < 16; kk++) {
            float4 a4 = *(const float4*)&As[kk][ty << 2];
            float4 b4 = *(const float4*)&Bs[kk][tx << 2];
            float a[4] = {a4.x, a4.y, a4.z, a4.w};
            float b[4] = {b4.x, b4.y, b4.z, b4.w};
#pragma unroll
            for (int i = 0; i < 4; i++)
#pragma unroll
                for (int j = 0; j < 4; j++) acc[i][j] += a[i] * b[j];
        }
        __syncthreads();
    }

#pragma unroll
    for (int i = 0; i < 4; i++) {
        int r = row0 + (ty << 2) + i;
        if (r < nrows) {
            float4 o = make_float4(acc[i][0], acc[i][1], acc[i][2], acc[i][3]);
            *(float4*)(g_PC + (size_t)r * dout2 + col0 + (tx << 2)) = o;
        }
    }
}

// ---------------- edge scatter: S[dst] += P[src] ----------------------------
__device__ __forceinline__ void red4(float* p, float4 v) {
    asm volatile("red.global.add.v4.f32 [%0], {%1,%2,%3,%4};"
                 :: "l"(p), "f"(v.x), "f"(v.y), "f"(v.z), "f"(v.w)
                 : "memory");
}

// dout = 128: one warp per edge; lane handles one float4 chunk.
// PC row = 256 floats = 64 float4; P part = first 32 float4.
__global__ void __launch_bounds__(256)
k_scatter128(const int* __restrict__ src, const int* __restrict__ dst) {
    int w    = (blockIdx.x * blockDim.x + threadIdx.x) >> 5;
    int lane = threadIdx.x & 31;
    if (w >= EE) return;
    int s = __ldg(&src[w]);
    int d = __ldg(&dst[w]);
    float4 v = *((const float4*)g_PC + (size_t)s * 64 + lane);
    red4(g_S + (size_t)d * 128 + lane * 4, v);
}

// dout = 64: two edges per warp; 16 lanes each.
// PC row = 128 floats = 32 float4; P part = first 16 float4. S row = 64 floats.
__global__ void __launch_bounds__(256)
k_scatter64(const int* __restrict__ src, const int* __restrict__ dst) {
    int tid  = blockIdx.x * blockDim.x + threadIdx.x;
    int w    = tid >> 5;
    int lane = threadIdx.x & 31;
    int sub  = lane >> 4, l = lane & 15;
    long long e = (long long)w * 2 + sub;
    if (e >= EE) return;
    int s = __ldg(&src[e]);
    int d = __ldg(&dst[e]);
    float4 v = *((const float4*)g_PC + (size_t)s * 32 + l);
    red4(g_S + (size_t)d * 64 + l * 4, v);
}

// ---------------- epilogue: out = act(S*cntinv + C + bias) ------------------
__global__ void __launch_bounds__(256)
k_epi(float* __restrict__ outext, int useH, int dout, int relu) {
    float* __restrict__ out = useH ? g_H : outext;
    int cpr = dout >> 2;  // float4 chunks per row
    int i = blockIdx.x * blockDim.x + threadIdx.x;
    if (i >= NN * cpr) return;
    int n = i / cpr, c = i % cpr;
    float inv = g_cntinv[n];
    float4 Sv = *(const float4*)(g_S + (size_t)n * dout + c * 4);
    float4 Cv = *(const float4*)(g_PC + (size_t)n * 2 * dout + dout + c * 4);
    float4 bv = *(const float4*)(g_bias + c * 4);
    float4 o;
    o.x = Sv.x * inv + Cv.x + bv.x;
    o.y = Sv.y * inv + Cv.y + bv.y;
    o.z = Sv.z * inv + Cv.z + bv.z;
    o.w = Sv.w * inv + Cv.w + bv.w;
    if (relu) {
        o.x = fmaxf(o.x, 0.f); o.y = fmaxf(o.y, 0.f);
        o.z = fmaxf(o.z, 0.f); o.w = fmaxf(o.w, 0.f);
    }
    *(float4*)(out + (size_t)n * dout + c * 4) = o;
}

// ---------------- launch ----------------------------------------------------
extern "C" void kernel_launch(void* const* d_in, const int* in_sizes, int n_in,
                              void* d_out, int out_size) {
    const float* x   = (const float*)d_in[0];
    const int*   ei  = (const int*)d_in[1];   // JAX default x64-disabled -> int32
    const int*   src = ei;
    const int*   dst = ei + EE;

    const float* Wl[3] = {(const float*)d_in[4],  (const float*)d_in[9],  (const float*)d_in[14]};
    const float* bl[3] = {(const float*)d_in[5],  (const float*)d_in[10], (const float*)d_in[15]};
    const float* Wr[3] = {(const float*)d_in[6],  (const float*)d_in[11], (const float*)d_in[16]};
    const float* Ws[3] = {(const float*)d_in[7],  (const float*)d_in[12], (const float*)d_in[17]};
    const float* bs[3] = {(const float*)d_in[8],  (const float*)d_in[13], (const float*)d_in[18]};

    const int TB = 256;

    // in-degree (shared across layers)
    k_zero_cnt<<<(NPAD + TB - 1) / TB, TB>>>();
    k_count<<<(EE + TB - 1) / TB, TB>>>(dst);
    k_inv<<<(NN + TB - 1) / TB, TB>>>();

    const int douts[3] = {128, 128, 64};
    for (int L = 0; L < 3; L++) {
        int dout  = douts[L];
        int dout2 = 2 * dout;
        int useH_in  = (L > 0) ? 1 : 0;
        int useH_out = (L < 2) ? 1 : 0;
        int relu     = (L < 2) ? 1 : 0;

        k_buildB<<<(128 * dout2 + TB - 1) / TB, TB>>>(Wl[L], Wr[L], Ws[L], bl[L], bs[L], dout);

        dim3 gg((NN + 63) / 64, dout2 / 64);
        k_gemm<<<gg, 256>>>(x, useH_in, NN, dout2);

        k_zero_S<<<(NN * dout + TB - 1) / TB, TB>>>(NN * dout);

        if (dout == 128) {
            long long threads = (long long)EE * 32;
            k_scatter128<<<(unsigned)((threads + TB - 1) / TB), TB>>>(src, dst);
        } else {
            long long threads = (long long)((EE + 1) / 2) * 32;
            k_scatter64<<<(unsigned)((threads + TB - 1) / TB), TB>>>(src, dst);
        }

        k_epi<<<(NN * (dout / 4) + TB - 1) / TB, TB>>>((float*)d_out, useH_out, dout, relu);
    }
}

// round 6
// speedup vs baseline: 1.3989x; 1.3989x over previous
#include <cuda_runtime.h>

#define NN   50000
#define EE   800000
#define NPAD 50048

// ---------------- scratch (device globals; no allocation allowed) -----------
__device__ __align__(16) float g_PC[(size_t)NPAD * 256];   // [P | C] fused GEMM output
__device__ __align__(16) float g_H [(size_t)NPAD * 128];   // layer activations
__device__ __align__(16) float g_B [128 * 256];            // [Wl | Wr+Ws] current layer
__device__ __align__(16) float g_bias[128];                // bl + bs current layer
__device__ int g_deg[NPAD];
__device__ int g_rowoff[NPAD + 1];
__device__ int g_fill[NPAD];
__device__ int g_srcl[EE];

// ---------------- packed f32x2 helpers ---------------------------------------
__device__ __forceinline__ void ffma2(unsigned long long& d, unsigned long long a,
                                      unsigned long long b) {
    asm("fma.rn.f32x2 %0, %1, %2, %0;" : "+l"(d) : "l"(a), "l"(b));
}
__device__ __forceinline__ unsigned long long pack2(float s) {
    unsigned long long d;
    asm("mov.b64 %0, {%1,%1};" : "=l"(d) : "f"(s));
    return d;
}
__device__ __forceinline__ void unpack2(unsigned long long v, float& lo, float& hi) {
    asm("mov.b64 {%0,%1}, %2;" : "=f"(lo), "=f"(hi) : "l"(v));
}

// ---------------- CSR build --------------------------------------------------
__global__ void k_zero_deg() {
    int i = blockIdx.x * blockDim.x + threadIdx.x;
    if (i < NPAD) g_deg[i] = 0;
}

__global__ void k_count(const int* __restrict__ dst) {
    int e = blockIdx.x * blockDim.x + threadIdx.x;
    if (e < EE) atomicAdd(&g_deg[dst[e]], 1);
}

// single block, 1024 threads: exclusive scan of g_deg -> g_rowoff / g_fill
__global__ void __launch_bounds__(1024) k_scan() {
    __shared__ int ssum[1024];
    int t = threadIdx.x;
    const int CH = (NN + 1023) / 1024;  // 49
    int b0 = t * CH;
    int e0 = min(b0 + CH, NN);
    int s = 0;
    for (int i = b0; i < e0; i++) s += g_deg[i];
    ssum[t] = s;
    __syncthreads();
    for (int d = 1; d < 1024; d <<= 1) {
        int v = (t >= d) ? ssum[t - d] : 0;
        __syncthreads();
        ssum[t] += v;
        __syncthreads();
    }
    int run = ssum[t] - s;   // exclusive prefix
    for (int i = b0; i < e0; i++) {
        g_rowoff[i] = run;
        g_fill[i]   = run;
        run += g_deg[i];
    }
    if (t == 1023) g_rowoff[NN] = run;
}

__global__ void k_place(const int* __restrict__ src, const int* __restrict__ dst) {
    int e = blockIdx.x * blockDim.x + threadIdx.x;
    if (e < EE) {
        int p = atomicAdd(&g_fill[dst[e]], 1);
        g_srcl[p] = src[e];
    }
}

// ---------------- weight prep: B = [Wl | Wr+Ws], bias = bl+bs ---------------
__global__ void k_buildB(const float* __restrict__ Wl, const float* __restrict__ Wr,
                         const float* __restrict__ Ws, const float* __restrict__ bl,
                         const float* __restrict__ bs, int dout) {
    int i = blockIdx.x * blockDim.x + threadIdx.x;
    int d2 = 2 * dout;
    if (i < 128 * d2) {
        int k = i / d2, j = i % d2;
        g_B[i] = (j < dout) ? Wl[k * dout + j]
                            : (Wr[k * dout + (j - dout)] + Ws[k * dout + (j - dout)]);
    }
    if (i < dout) g_bias[i] = bl[i] + bs[i];
}

// ---------------- SGEMM: PC[n,dout2] = A[n,128] @ g_B[128,dout2] ------------
// 128x128 tile, BK=8, 256 threads, 8x8 microtile, f32x2 packed FMA.
__global__ void __launch_bounds__(256)
k_gemm(const float* __restrict__ Aext, int useH, int nrows, int dout2) {
    const float* __restrict__ A = useH ? g_H : Aext;
    __shared__ float As[8][128];
    __shared__ float Bs[8][128];

    int t   = threadIdx.x;
    int tx  = t & 15;        // n-dim
    int ty  = t >> 4;        // m-dim
    int m0  = ty * 8;
    int row0 = blockIdx.x * 128;
    int col0 = blockIdx.y * 128;

    int fa_r = t >> 1;          // A fill: row (0..127)
    int fa_k = (t & 1) * 4;     // A fill: k quad
    int fb_k = t >> 5;          // B fill: k row (0..7)
    int fb_n = (t & 31) * 4;    // B fill: n col

    unsigned long long acc[4][8];
#pragma unroll
    for (int mp = 0; mp < 4; mp++)
#pragma unroll
        for (int n = 0; n < 8; n++) acc[mp][n] = 0ULL;

    for (int k0 = 0; k0 < 128; k0 += 8) {
        float4 av = make_float4(0.f, 0.f, 0.f, 0.f);
        int ar = row0 + fa_r;
        if (ar < nrows) av = *(const float4*)(A + (size_t)ar * 128 + k0 + fa_k);
        As[fa_k + 0][fa_r] = av.x;
        As[fa_k + 1][fa_r] = av.y;
        As[fa_k + 2][fa_r] = av.z;
        As[fa_k + 3][fa_r] = av.w;

        float4 bv = *(const float4*)(g_B + (size_t)(k0 + fb_k) * dout2 + col0 + fb_n);
        *(float4*)&Bs[fb_k][fb_n] = bv;
        __syncthreads();

#pragma unroll
        for (int kk = 0; kk < 8; kk++) {
            ulonglong2 a01 = *(const ulonglong2*)&As[kk][m0];
            ulonglong2 a23 = *(const ulonglong2*)&As[kk][m0 + 4];
            float4 bA = *(const float4*)&Bs[kk][tx * 4];        // cols 4tx..+3
            float4 bB = *(const float4*)&Bs[kk][tx * 4 + 64];   // cols 4tx+64..+67
            unsigned long long avp[4] = {a01.x, a01.y, a23.x, a23.y};
            unsigned long long bd[8];
            bd[0] = pack2(bA.x); bd[1] = pack2(bA.y);
            bd[2] = pack2(bA.z); bd[3] = pack2(bA.w);
            bd[4] = pack2(bB.x); bd[5] = pack2(bB.y);
            bd[6] = pack2(bB.z); bd[7] = pack2(bB.w);
#pragma unroll
            for (int mp = 0; mp < 4; mp++)
#pragma unroll
                for (int n = 0; n < 8; n++) ffma2(acc[mp][n], avp[mp], bd[n]);
        }
        __syncthreads();
    }

#pragma unroll
    for (int mp = 0; mp < 4; mp++) {
        float lo[8], hi[8];
#pragma unroll
        for (int n = 0; n < 8; n++) unpack2(acc[mp][n], lo[n], hi[n]);
        int r0 = row0 + m0 + 2 * mp;
        if (r0 < nrows) {
            *(float4*)(g_PC + (size_t)r0 * dout2 + col0 + tx * 4) =
                make_float4(lo[0], lo[1], lo[2], lo[3]);
            *(float4*)(g_PC + (size_t)r0 * dout2 + col0 + tx * 4 + 64) =
                make_float4(lo[4], lo[5], lo[6], lo[7]);
        }
        if (r0 + 1 < nrows) {
            *(float4*)(g_PC + (size_t)(r0 + 1) * dout2 + col0 + tx * 4) =
                make_float4(hi[0], hi[1], hi[2], hi[3]);
            *(float4*)(g_PC + (size_t)(r0 + 1) * dout2 + col0 + tx * 4 + 64) =
                make_float4(hi[4], hi[5], hi[6], hi[7]);
        }
    }
}

// ---------------- fused aggregate + epilogue --------------------------------
// CPR = float4 chunks per row (32 for dout=128, 16 for dout=64).
// useH != 0 -> write g_H, else write `outext`.
template <int CPR>
__global__ void __launch_bounds__(256)
k_agg(float* __restrict__ outext, int useH, int relu) {
    float* __restrict__ out = useH ? g_H : outext;
    int gid  = blockIdx.x * blockDim.x + threadIdx.x;
    int node = gid / CPR;
    int c    = gid % CPR;
    if (node >= NN) return;
    int beg = g_rowoff[node];
    int end = g_rowoff[node + 1];

    const float4* PC4 = (const float4*)g_PC;
    float4 acc = make_float4(0.f, 0.f, 0.f, 0.f);
#pragma unroll 4
    for (int j = beg; j < end; j++) {
        int s = __ldg(&g_srcl[j]);
        float4 v = PC4[(size_t)s * (2 * CPR) + c];
        acc.x += v.x; acc.y += v.y; acc.z += v.z; acc.w += v.w;
    }
    float inv = 1.0f / fmaxf((float)(end - beg), 1.0f);
    float4 Cv = PC4[(size_t)node * (2 * CPR) + CPR + c];
    float4 bv = ((const float4*)g_bias)[c];
    float4 o;
    o.x = acc.x * inv + Cv.x + bv.x;
    o.y = acc.y * inv + Cv.y + bv.y;
    o.z = acc.z * inv + Cv.z + bv.z;
    o.w = acc.w * inv + Cv.w + bv.w;
    if (relu) {
        o.x = fmaxf(o.x, 0.f); o.y = fmaxf(o.y, 0.f);
        o.z = fmaxf(o.z, 0.f); o.w = fmaxf(o.w, 0.f);
    }
    ((float4*)out)[(size_t)node * CPR + c] = o;
}

// ---------------- launch ----------------------------------------------------
extern "C" void kernel_launch(void* const* d_in, const int* in_sizes, int n_in,
                              void* d_out, int out_size) {
    const float* x   = (const float*)d_in[0];
    const int*   ei  = (const int*)d_in[1];   // JAX x64 disabled -> int32
    const int*   src = ei;
    const int*   dst = ei + EE;

    const float* Wl[3] = {(const float*)d_in[4],  (const float*)d_in[9],  (const float*)d_in[14]};
    const float* bl[3] = {(const float*)d_in[5],  (const float*)d_in[10], (const float*)d_in[15]};
    const float* Wr[3] = {(const float*)d_in[6],  (const float*)d_in[11], (const float*)d_in[16]};
    const float* Ws[3] = {(const float*)d_in[7],  (const float*)d_in[12], (const float*)d_in[17]};
    const float* bs[3] = {(const float*)d_in[8],  (const float*)d_in[13], (const float*)d_in[18]};

    const int TB = 256;

    // CSR build (shared across layers)
    k_zero_deg<<<(NPAD + TB - 1) / TB, TB>>>();
    k_count<<<(EE + TB - 1) / TB, TB>>>(dst);
    k_scan<<<1, 1024>>>();
    k_place<<<(EE + TB - 1) / TB, TB>>>(src, dst);

    const int douts[3] = {128, 128, 64};
    for (int L = 0; L < 3; L++) {
        int dout  = douts[L];
        int dout2 = 2 * dout;
        int useH_in  = (L > 0) ? 1 : 0;
        int useH_out = (L < 2) ? 1 : 0;
        int relu     = (L < 2) ? 1 : 0;

        k_buildB<<<(128 * dout2 + TB - 1) / TB, TB>>>(Wl[L], Wr[L], Ws[L], bl[L], bs[L], dout);

        dim3 gg((NN + 127) / 128, dout2 / 128);
        k_gemm<<<gg, 256>>>(x, useH_in, NN, dout2);

        if (dout == 128) {
            int total = NN * 32;
            k_agg<32><<<(total + TB - 1) / TB, TB>>>((float*)d_out, useH_out, relu);
        } else {
            int total = NN * 16;
            k_agg<16><<<(total + TB - 1) / TB, TB>>>((float*)d_out, useH_out, relu);
        }
    }
}

// round 8
// speedup vs baseline: 1.8306x; 1.3086x over previous
#include <cuda_runtime.h>
#include <cuda_bf16.h>
#include <cstdint>

#define NN    50000
#define EE    800000
#define NPAD  50048
#define NTILES (NPAD / 128)          // 391 row-tiles of 128

// ---------------- scratch (device globals; no allocation allowed) -----------
__device__ __align__(16) float g_PC[(size_t)NPAD * 256];   // [P | C] GEMM output
__device__ __align__(16) float g_H [(size_t)NPAD * 128];   // layer activations
__device__ __align__(16) float g_bias[128];                // bl + bs current layer
// A images in mma-fragment layout: [r16 group][kstep][lane] = uint4 (16B/lane)
__device__ uint4 g_Ahi4[(size_t)NPAD * 16];
__device__ uint4 g_Alo4[(size_t)NPAD * 16];
// B images: [ntile][kstep][lane] = uint2 (8B/lane); max dout2=256 -> 32 ntiles
__device__ uint2 g_Bhi2[32 * 8 * 32];
__device__ uint2 g_Blo2[32 * 8 * 32];
__device__ int g_deg[NPAD];
__device__ int g_rowoff[NPAD + 1];
__device__ int g_fill[NPAD];
__device__ int g_srcl[EE];

// ---------------- helpers ----------------------------------------------------
__device__ __forceinline__ void mma16816(float* c, const uint4& a, const uint2& b) {
    asm("mma.sync.aligned.m16n8k16.row.col.f32.bf16.bf16.f32 "
        "{%0,%1,%2,%3}, {%4,%5,%6,%7}, {%8,%9}, {%0,%1,%2,%3};"
        : "+f"(c[0]), "+f"(c[1]), "+f"(c[2]), "+f"(c[3])
        : "r"(a.x), "r"(a.y), "r"(a.z), "r"(a.w), "r"(b.x), "r"(b.y));
}

// split a float pair into packed-bf16x2 hi word and lo word
__device__ __forceinline__ void split2(float f0, float f1, uint32_t& hw, uint32_t& lw) {
    __nv_bfloat16 h0 = __float2bfloat16(f0);
    __nv_bfloat16 h1 = __float2bfloat16(f1);
    __nv_bfloat16 l0 = __float2bfloat16(f0 - __bfloat162float(h0));
    __nv_bfloat16 l1 = __float2bfloat16(f1 - __bfloat162float(h1));
    hw = (uint32_t)__bfloat16_as_ushort(h0) | ((uint32_t)__bfloat16_as_ushort(h1) << 16);
    lw = (uint32_t)__bfloat16_as_ushort(l0) | ((uint32_t)__bfloat16_as_ushort(l1) << 16);
}

// ---------------- CSR build --------------------------------------------------
__global__ void k_zero_deg() {
    int i = blockIdx.x * blockDim.x + threadIdx.x;
    if (i < NPAD) g_deg[i] = 0;
}
__global__ void k_count(const int* __restrict__ dst) {
    int e = blockIdx.x * blockDim.x + threadIdx.x;
    if (e < EE) atomicAdd(&g_deg[dst[e]], 1);
}
__global__ void __launch_bounds__(1024) k_scan() {
    __shared__ int ssum[1024];
    int t = threadIdx.x;
    const int CH = (NN + 1023) / 1024;
    int b0 = t * CH;
    int e0 = min(b0 + CH, NN);
    int s = 0;
    for (int i = b0; i < e0; i++) s += g_deg[i];
    ssum[t] = s;
    __syncthreads();
    for (int d = 1; d < 1024; d <<= 1) {
        int v = (t >= d) ? ssum[t - d] : 0;
        __syncthreads();
        ssum[t] += v;
        __syncthreads();
    }
    int run = ssum[t] - s;
    for (int i = b0; i < e0; i++) {
        g_rowoff[i] = run;
        g_fill[i]   = run;
        run += g_deg[i];
    }
    if (t == 1023) g_rowoff[NN] = run;
}
__global__ void k_place(const int* __restrict__ src, const int* __restrict__ dst) {
    int e = blockIdx.x * blockDim.x + threadIdx.x;
    if (e < EE) {
        int p = atomicAdd(&g_fill[dst[e]], 1);
        g_srcl[p] = src[e];
    }
}

// ---------------- convA: fp32 [NPAD,128] -> fragment-layout bf16 hi/lo ------
// item idx: r16 = idx/256, ks = (idx>>5)&7, lane = idx&31
// fragment elems: a0=(r,c),(r,c+1)  a1=(r+8,c),(r+8,c+1)
//                 a2=(r,c+8),(r,c+9) a3=(r+8,c+8),(r+8,c+9)
// with r = r16*16 + lane/4, c = ks*16 + (lane%4)*2
__global__ void __launch_bounds__(256)
k_convA(const float* __restrict__ Aext, int useH) {
    const float* __restrict__ A = useH ? g_H : Aext;
    int idx = blockIdx.x * blockDim.x + threadIdx.x;
    if (idx >= NPAD * 16) return;
    int r16  = idx >> 8;
    int ks   = (idx >> 5) & 7;
    int lane = idx & 31;
    int r = r16 * 16 + (lane >> 2);
    int c = ks * 16 + (lane & 3) * 2;

    float2 p00 = (r     < NN) ? *(const float2*)(A + (size_t)r * 128 + c)
                              : make_float2(0.f, 0.f);
    float2 p10 = (r + 8 < NN) ? *(const float2*)(A + (size_t)(r + 8) * 128 + c)
                              : make_float2(0.f, 0.f);
    float2 p01 = (r     < NN) ? *(const float2*)(A + (size_t)r * 128 + c + 8)
                              : make_float2(0.f, 0.f);
    float2 p11 = (r + 8 < NN) ? *(const float2*)(A + (size_t)(r + 8) * 128 + c + 8)
                              : make_float2(0.f, 0.f);

    uint4 hv, lv;
    split2(p00.x, p00.y, hv.x, lv.x);
    split2(p10.x, p10.y, hv.y, lv.y);
    split2(p01.x, p01.y, hv.z, lv.z);
    split2(p11.x, p11.y, hv.w, lv.w);
    g_Ahi4[idx] = hv;
    g_Alo4[idx] = lv;
}

// ---------------- convB: fused [Wl | Wr+Ws] -> fragment-layout hi/lo + bias -
// item idx over (dout2/8) ntiles * 8 ks * 32 lanes.
// b0 = (k0,n),(k0+1,n);  b1 = (k0+8,n),(k0+9,n)
// with n = ntile*8 + lane/4, k0 = ks*16 + (lane%4)*2
__global__ void __launch_bounds__(256)
k_convB(const float* __restrict__ Wl, const float* __restrict__ Wr,
        const float* __restrict__ Ws, const float* __restrict__ bl,
        const float* __restrict__ bs, int dout) {
    int dout2 = 2 * dout;
    int items = (dout2 / 8) * 256;
    int idx = blockIdx.x * blockDim.x + threadIdx.x;
    if (idx < items) {
        int ntile = idx >> 8;
        int ks    = (idx >> 5) & 7;
        int lane  = idx & 31;
        int n  = ntile * 8 + (lane >> 2);
        int k0 = ks * 16 + (lane & 3) * 2;

        float v[4];
#pragma unroll
        for (int i = 0; i < 4; i++) {
            int k = k0 + (i >> 1) * 8 + (i & 1);
            v[i] = (n < dout) ? Wl[k * dout + n]
                              : Wr[k * dout + (n - dout)] + Ws[k * dout + (n - dout)];
        }
        uint2 hv, lv;
        split2(v[0], v[1], hv.x, lv.x);
        split2(v[2], v[3], hv.y, lv.y);
        g_Bhi2[idx] = hv;
        g_Blo2[idx] = lv;
    }
    if (idx < dout) g_bias[idx] = bl[idx] + bs[idx];
}

// ---------------- HMMA GEMM: PC[128 tile rows, dout2] -----------------------
// block = 8 warps: warpRow = wid&3 (32 rows each), warpCol = wid>>2 (64 cols).
// Per warp: 2 m-tiles x 8 n-tiles, K=128 as 8 ksteps; 3-product bf16 split.
__global__ void __launch_bounds__(256)
k_mm(int dout2) {
    int tid = threadIdx.x, wid = tid >> 5, lane = tid & 31;
    int wr = wid & 3, wc = wid >> 2;
    int tileRow = blockIdx.x, colB = blockIdx.y;
    int r16b = tileRow * 8 + wr * 2;        // row16-group of m-tile 0
    int ntb  = colB * 16 + wc * 8;          // first n-tile index

    float acc[2][8][4];
#pragma unroll
    for (int m = 0; m < 2; m++)
#pragma unroll
        for (int j = 0; j < 8; j++)
#pragma unroll
            for (int q = 0; q < 4; q++) acc[m][j][q] = 0.f;

#pragma unroll
    for (int ks = 0; ks < 8; ks++) {
        uint4 ah0 = g_Ahi4[((size_t)(r16b + 0) * 8 + ks) * 32 + lane];
        uint4 ah1 = g_Ahi4[((size_t)(r16b + 1) * 8 + ks) * 32 + lane];
        uint4 al0 = g_Alo4[((size_t)(r16b + 0) * 8 + ks) * 32 + lane];
        uint4 al1 = g_Alo4[((size_t)(r16b + 1) * 8 + ks) * 32 + lane];
        uint2 bh[8], bl_[8];
#pragma unroll
        for (int j = 0; j < 8; j++) {
            bh[j]  = g_Bhi2[((ntb + j) * 8 + ks) * 32 + lane];
            bl_[j] = g_Blo2[((ntb + j) * 8 + ks) * 32 + lane];
        }
#pragma unroll
        for (int j = 0; j < 8; j++) {
            mma16816(acc[0][j], ah0, bh[j]);
            mma16816(acc[1][j], ah1, bh[j]);
            mma16816(acc[0][j], ah0, bl_[j]);
            mma16816(acc[1][j], ah1, bl_[j]);
            mma16816(acc[0][j], al0, bh[j]);
            mma16816(acc[1][j], al1, bh[j]);
        }
    }

    // store: c0,c1 -> (r, col..col+1); c2,c3 -> (r+8, col..col+1)
#pragma unroll
    for (int m = 0; m < 2; m++) {
        int r = tileRow * 128 + wr * 32 + m * 16 + (lane >> 2);
#pragma unroll
        for (int j = 0; j < 8; j++) {
            int col = colB * 128 + wc * 64 + j * 8 + (lane & 3) * 2;
            *(float2*)(g_PC + (size_t)r * dout2 + col) =
                make_float2(acc[m][j][0], acc[m][j][1]);
            *(float2*)(g_PC + (size_t)(r + 8) * dout2 + col) =
                make_float2(acc[m][j][2], acc[m][j][3]);
        }
    }
}

// ---------------- fused aggregate + epilogue --------------------------------
template <int CPR>
__global__ void __launch_bounds__(256)
k_agg(float* __restrict__ outext, int useH, int relu) {
    float* __restrict__ out = useH ? g_H : outext;
    int gid  = blockIdx.x * blockDim.x + threadIdx.x;
    int node = gid / CPR;
    int c    = gid % CPR;
    if (node >= NN) return;
    int beg = g_rowoff[node];
    int end = g_rowoff[node + 1];

    const float4* PC4 = (const float4*)g_PC;
    float4 acc = make_float4(0.f, 0.f, 0.f, 0.f);
#pragma unroll 4
    for (int j = beg; j < end; j++) {
        int s = __ldg(&g_srcl[j]);
        float4 v = PC4[(size_t)s * (2 * CPR) + c];
        acc.x += v.x; acc.y += v.y; acc.z += v.z; acc.w += v.w;
    }
    float inv = 1.0f / fmaxf((float)(end - beg), 1.0f);
    float4 Cv = PC4[(size_t)node * (2 * CPR) + CPR + c];
    float4 bv = ((const float4*)g_bias)[c];
    float4 o;
    o.x = acc.x * inv + Cv.x + bv.x;
    o.y = acc.y * inv + Cv.y + bv.y;
    o.z = acc.z * inv + Cv.z + bv.z;
    o.w = acc.w * inv + Cv.w + bv.w;
    if (relu) {
        o.x = fmaxf(o.x, 0.f); o.y = fmaxf(o.y, 0.f);
        o.z = fmaxf(o.z, 0.f); o.w = fmaxf(o.w, 0.f);
    }
    ((float4*)out)[(size_t)node * CPR + c] = o;
}

// ---------------- launch ----------------------------------------------------
extern "C" void kernel_launch(void* const* d_in, const int* in_sizes, int n_in,
                              void* d_out, int out_size) {
    const float* x   = (const float*)d_in[0];
    const int*   ei  = (const int*)d_in[1];   // JAX x64 disabled -> int32
    const int*   src = ei;
    const int*   dst = ei + EE;

    const float* Wl[3] = {(const float*)d_in[4],  (const float*)d_in[9],  (const float*)d_in[14]};
    const float* bl[3] = {(const float*)d_in[5],  (const float*)d_in[10], (const float*)d_in[15]};
    const float* Wr[3] = {(const float*)d_in[6],  (const float*)d_in[11], (const float*)d_in[16]};
    const float* Ws[3] = {(const float*)d_in[7],  (const float*)d_in[12], (const float*)d_in[17]};
    const float* bs[3] = {(const float*)d_in[8],  (const float*)d_in[13], (const float*)d_in[18]};

    const int TB = 256;

    // CSR build (shared across layers)
    k_zero_deg<<<(NPAD + TB - 1) / TB, TB>>>();
    k_count<<<(EE + TB - 1) / TB, TB>>>(dst);
    k_scan<<<1, 1024>>>();
    k_place<<<(EE + TB - 1) / TB, TB>>>(src, dst);

    const int douts[3] = {128, 128, 64};
    for (int L = 0; L < 3; L++) {
        int dout  = douts[L];
        int dout2 = 2 * dout;
        int useH_in  = (L > 0) ? 1 : 0;
        int useH_out = (L < 2) ? 1 : 0;
        int relu     = (L < 2) ? 1 : 0;

        int bItems = (dout2 / 8) * 256;
        k_convB<<<(bItems + TB - 1) / TB, TB>>>(Wl[L], Wr[L], Ws[L], bl[L], bs[L], dout);
        k_convA<<<(NPAD * 16 + TB - 1) / TB, TB>>>(x, useH_in);

        dim3 gg(NTILES, dout2 / 128);
        k_mm<<<gg, 256>>>(dout2);

        if (dout == 128) {
            k_agg<32><<<(NN * 32 + TB - 1) / TB, TB>>>((float*)d_out, useH_out, relu);
        } else {
            k_agg<16><<<(NN * 16 + TB - 1) / TB, TB>>>((float*)d_out, useH_out, relu);
        }
    }
}

// round 9
// speedup vs baseline: 1.8807x; 1.0273x over previous
#include <cuda_runtime.h>
#include <cuda_bf16.h>
#include <cuda_fp16.h>
#include <cstdint>

#define NN    50000
#define EE    800000
#define NPAD  50048
#define NTILES (NPAD / 128)          // 391 row-tiles of 128

// ---------------- scratch (device globals; no allocation allowed) -----------
__device__ __align__(16) __half g_Pv[(size_t)NPAD * 128];  // projected (for gather), fp16
__device__ __align__(16) float  g_C [(size_t)NPAD * 128];  // self term, fp32
__device__ __align__(16) float  g_bias[128];               // bl + bs current layer
// A images in mma-fragment layout: [r16 group][kstep][lane] = uint4
__device__ uint4 g_Ahi4[(size_t)NPAD * 16];
__device__ uint4 g_Alo4[(size_t)NPAD * 16];
// B images: [ntile][kstep][lane] = uint2; max dout2=256 -> 32 ntiles
__device__ uint2 g_Bhi2[32 * 8 * 32];
__device__ uint2 g_Blo2[32 * 8 * 32];
__device__ int g_deg[NPAD];
__device__ int g_rowoff[NPAD + 1];
__device__ int g_fill[NPAD];
__device__ int g_srcl[EE];

// ---------------- helpers ----------------------------------------------------
__device__ __forceinline__ void mma16816(float* c, const uint4& a, const uint2& b) {
    asm("mma.sync.aligned.m16n8k16.row.col.f32.bf16.bf16.f32 "
        "{%0,%1,%2,%3}, {%4,%5,%6,%7}, {%8,%9}, {%0,%1,%2,%3};"
        : "+f"(c[0]), "+f"(c[1]), "+f"(c[2]), "+f"(c[3])
        : "r"(a.x), "r"(a.y), "r"(a.z), "r"(a.w), "r"(b.x), "r"(b.y));
}

__device__ __forceinline__ void split2(float f0, float f1, uint32_t& hw, uint32_t& lw) {
    __nv_bfloat16 h0 = __float2bfloat16(f0);
    __nv_bfloat16 h1 = __float2bfloat16(f1);
    __nv_bfloat16 l0 = __float2bfloat16(f0 - __bfloat162float(h0));
    __nv_bfloat16 l1 = __float2bfloat16(f1 - __bfloat162float(h1));
    hw = (uint32_t)__bfloat16_as_ushort(h0) | ((uint32_t)__bfloat16_as_ushort(h1) << 16);
    lw = (uint32_t)__bfloat16_as_ushort(l0) | ((uint32_t)__bfloat16_as_ushort(l1) << 16);
}

// ---------------- CSR build --------------------------------------------------
__global__ void k_zero_deg() {
    int i = blockIdx.x * blockDim.x + threadIdx.x;
    if (i < NPAD) g_deg[i] = 0;
}
__global__ void k_count(const int* __restrict__ dst) {
    int e = blockIdx.x * blockDim.x + threadIdx.x;
    if (e < EE) atomicAdd(&g_deg[dst[e]], 1);
}
__global__ void __launch_bounds__(1024) k_scan() {
    __shared__ int ssum[1024];
    int t = threadIdx.x;
    const int CH = (NN + 1023) / 1024;
    int b0 = t * CH;
    int e0 = min(b0 + CH, NN);
    int s = 0;
    for (int i = b0; i < e0; i++) s += g_deg[i];
    ssum[t] = s;
    __syncthreads();
    for (int d = 1; d < 1024; d <<= 1) {
        int v = (t >= d) ? ssum[t - d] : 0;
        __syncthreads();
        ssum[t] += v;
        __syncthreads();
    }
    int run = ssum[t] - s;
    for (int i = b0; i < e0; i++) {
        g_rowoff[i] = run;
        g_fill[i]   = run;
        run += g_deg[i];
    }
    if (t == 1023) g_rowoff[NN] = run;
}
__global__ void k_place(const int* __restrict__ src, const int* __restrict__ dst) {
    int e = blockIdx.x * blockDim.x + threadIdx.x;
    if (e < EE) {
        int p = atomicAdd(&g_fill[dst[e]], 1);
        g_srcl[p] = src[e];
    }
}

// ---------------- convA: fp32 x[N,128] -> fragment-layout bf16 hi/lo --------
// (layer-0 only; later layers' fragments are written directly by k_agg)
__global__ void __launch_bounds__(256)
k_convA(const float* __restrict__ A) {
    int idx = blockIdx.x * blockDim.x + threadIdx.x;
    if (idx >= NPAD * 16) return;
    int r16  = idx >> 8;
    int ks   = (idx >> 5) & 7;
    int lane = idx & 31;
    int r = r16 * 16 + (lane >> 2);
    int c = ks * 16 + (lane & 3) * 2;

    float2 p00 = (r     < NN) ? *(const float2*)(A + (size_t)r * 128 + c)
                              : make_float2(0.f, 0.f);
    float2 p10 = (r + 8 < NN) ? *(const float2*)(A + (size_t)(r + 8) * 128 + c)
                              : make_float2(0.f, 0.f);
    float2 p01 = (r     < NN) ? *(const float2*)(A + (size_t)r * 128 + c + 8)
                              : make_float2(0.f, 0.f);
    float2 p11 = (r + 8 < NN) ? *(const float2*)(A + (size_t)(r + 8) * 128 + c + 8)
                              : make_float2(0.f, 0.f);

    uint4 hv, lv;
    split2(p00.x, p00.y, hv.x, lv.x);
    split2(p10.x, p10.y, hv.y, lv.y);
    split2(p01.x, p01.y, hv.z, lv.z);
    split2(p11.x, p11.y, hv.w, lv.w);
    g_Ahi4[idx] = hv;
    g_Alo4[idx] = lv;
}

// ---------------- convB: fused [Wl | Wr+Ws] -> fragment hi/lo + bias --------
__global__ void __launch_bounds__(256)
k_convB(const float* __restrict__ Wl, const float* __restrict__ Wr,
        const float* __restrict__ Ws, const float* __restrict__ bl,
        const float* __restrict__ bs, int dout) {
    int dout2 = 2 * dout;
    int items = (dout2 / 8) * 256;
    int idx = blockIdx.x * blockDim.x + threadIdx.x;
    if (idx < items) {
        int ntile = idx >> 8;
        int ks    = (idx >> 5) & 7;
        int lane  = idx & 31;
        int n  = ntile * 8 + (lane >> 2);
        int k0 = ks * 16 + (lane & 3) * 2;

        float v[4];
#pragma unroll
        for (int i = 0; i < 4; i++) {
            int k = k0 + (i >> 1) * 8 + (i & 1);
            v[i] = (n < dout) ? Wl[k * dout + n]
                              : Wr[k * dout + (n - dout)] + Ws[k * dout + (n - dout)];
        }
        uint2 hv, lv;
        split2(v[0], v[1], hv.x, lv.x);
        split2(v[2], v[3], hv.y, lv.y);
        g_Bhi2[idx] = hv;
        g_Blo2[idx] = lv;
    }
    if (idx < dout) g_bias[idx] = bl[idx] + bs[idx];
}

// ---------------- HMMA GEMM -> P (fp16) and C (fp32) ------------------------
__global__ void __launch_bounds__(256)
k_mm(int dout) {
    int dout2 = 2 * dout;
    int tid = threadIdx.x, wid = tid >> 5, lane = tid & 31;
    int wr = wid & 3, wc = wid >> 2;
    int tileRow = blockIdx.x, colB = blockIdx.y;
    int r16b = tileRow * 8 + wr * 2;
    int ntb  = colB * 16 + wc * 8;

    float acc[2][8][4];
#pragma unroll
    for (int m = 0; m < 2; m++)
#pragma unroll
        for (int j = 0; j < 8; j++)
#pragma unroll
            for (int q = 0; q < 4; q++) acc[m][j][q] = 0.f;

#pragma unroll
    for (int ks = 0; ks < 8; ks++) {
        uint4 ah0 = g_Ahi4[((size_t)(r16b + 0) * 8 + ks) * 32 + lane];
        uint4 ah1 = g_Ahi4[((size_t)(r16b + 1) * 8 + ks) * 32 + lane];
        uint4 al0 = g_Alo4[((size_t)(r16b + 0) * 8 + ks) * 32 + lane];
        uint4 al1 = g_Alo4[((size_t)(r16b + 1) * 8 + ks) * 32 + lane];
        uint2 bh[8], bl_[8];
#pragma unroll
        for (int j = 0; j < 8; j++) {
            bh[j]  = g_Bhi2[((ntb + j) * 8 + ks) * 32 + lane];
            bl_[j] = g_Blo2[((ntb + j) * 8 + ks) * 32 + lane];
        }
#pragma unroll
        for (int j = 0; j < 8; j++) {
            mma16816(acc[0][j], ah0, bh[j]);
            mma16816(acc[1][j], ah1, bh[j]);
            mma16816(acc[0][j], ah0, bl_[j]);
            mma16816(acc[1][j], ah1, bl_[j]);
            mma16816(acc[0][j], al0, bh[j]);
            mma16816(acc[1][j], al1, bh[j]);
        }
    }

#pragma unroll
    for (int m = 0; m < 2; m++) {
        int r = tileRow * 128 + wr * 32 + m * 16 + (lane >> 2);
#pragma unroll
        for (int j = 0; j < 8; j++) {
            int col = colB * 128 + wc * 64 + j * 8 + (lane & 3) * 2;
            if (col < dout) {
                *(__half2*)(g_Pv + (size_t)r * dout + col) =
                    __floats2half2_rn(acc[m][j][0], acc[m][j][1]);
                *(__half2*)(g_Pv + (size_t)(r + 8) * dout + col) =
                    __floats2half2_rn(acc[m][j][2], acc[m][j][3]);
            } else {
                int cc = col - dout;
                *(float2*)(g_C + (size_t)r * dout + cc) =
                    make_float2(acc[m][j][0], acc[m][j][1]);
                *(float2*)(g_C + (size_t)(r + 8) * dout + cc) =
                    make_float2(acc[m][j][2], acc[m][j][3]);
            }
        }
    }
}

// ---------------- fused aggregate + epilogue + fragment write ---------------
// CPR8 threads per node, 8 cols each. writeOut: fp32 to `out`; else write
// next-layer A fragments (bf16 hi/lo) directly.
template <int CPR8, int DOUT>
__global__ void __launch_bounds__(256)
k_agg(float* __restrict__ out, int writeOut, int relu) {
    int gid  = blockIdx.x * blockDim.x + threadIdx.x;
    int node = gid / CPR8;
    int cidx = gid % CPR8;
    if (node >= NN) return;
    int c0  = cidx * 8;
    int beg = g_rowoff[node];
    int end = g_rowoff[node + 1];

    const uint4* P4 = (const uint4*)g_Pv;
    float acc[8];
#pragma unroll
    for (int i = 0; i < 8; i++) acc[i] = 0.f;

    for (int j = beg; j < end; j++) {
        int s = __ldg(&g_srcl[j]);
        uint4 v = P4[(size_t)s * CPR8 + cidx];
        uint32_t w[4] = {v.x, v.y, v.z, v.w};
#pragma unroll
        for (int q = 0; q < 4; q++) {
            float2 f = __half22float2(*(__half2*)&w[q]);
            acc[2 * q]     += f.x;
            acc[2 * q + 1] += f.y;
        }
    }
    float inv = 1.0f / fmaxf((float)(end - beg), 1.0f);

    float4 C0 = *(const float4*)(g_C + (size_t)node * DOUT + c0);
    float4 C1 = *(const float4*)(g_C + (size_t)node * DOUT + c0 + 4);
    float4 b0 = *(const float4*)(g_bias + c0);
    float4 b1 = *(const float4*)(g_bias + c0 + 4);
    float o[8];
    o[0] = acc[0] * inv + C0.x + b0.x;  o[1] = acc[1] * inv + C0.y + b0.y;
    o[2] = acc[2] * inv + C0.z + b0.z;  o[3] = acc[3] * inv + C0.w + b0.w;
    o[4] = acc[4] * inv + C1.x + b1.x;  o[5] = acc[5] * inv + C1.y + b1.y;
    o[6] = acc[6] * inv + C1.z + b1.z;  o[7] = acc[7] * inv + C1.w + b1.w;
    if (relu) {
#pragma unroll
        for (int i = 0; i < 8; i++) o[i] = fmaxf(o[i], 0.f);
    }

    if (writeOut) {
        *(float4*)(out + (size_t)node * DOUT + c0)     = make_float4(o[0], o[1], o[2], o[3]);
        *(float4*)(out + (size_t)node * DOUT + c0 + 4) = make_float4(o[4], o[5], o[6], o[7]);
    } else {
        // write bf16 hi/lo fragments for next layer's A (row=node, cols c0..c0+7)
        int r16  = node >> 4;
        int ks   = c0 >> 4;
        int word = (((c0 >> 3) & 1) << 1) | ((node >> 3) & 1);
        uint32_t* AH = (uint32_t*)g_Ahi4;
        uint32_t* AL = (uint32_t*)g_Alo4;
        size_t base = ((size_t)r16 * 256 + (size_t)ks * 32) * 4;
#pragma unroll
        for (int p = 0; p < 4; p++) {
            int lane = ((node & 7) << 2) | p;
            uint32_t hw, lw;
            split2(o[2 * p], o[2 * p + 1], hw, lw);
            AH[base + lane * 4 + word] = hw;
            AL[base + lane * 4 + word] = lw;
        }
    }
}

// ---------------- launch ----------------------------------------------------
extern "C" void kernel_launch(void* const* d_in, const int* in_sizes, int n_in,
                              void* d_out, int out_size) {
    const float* x   = (const float*)d_in[0];
    const int*   ei  = (const int*)d_in[1];   // JAX x64 disabled -> int32
    const int*   src = ei;
    const int*   dst = ei + EE;

    const float* Wl[3] = {(const float*)d_in[4],  (const float*)d_in[9],  (const float*)d_in[14]};
    const float* bl[3] = {(const float*)d_in[5],  (const float*)d_in[10], (const float*)d_in[15]};
    const float* Wr[3] = {(const float*)d_in[6],  (const float*)d_in[11], (const float*)d_in[16]};
    const float* Ws[3] = {(const float*)d_in[7],  (const float*)d_in[12], (const float*)d_in[17]};
    const float* bs[3] = {(const float*)d_in[8],  (const float*)d_in[13], (const float*)d_in[18]};

    const int TB = 256;

    // CSR build (shared across layers)
    k_zero_deg<<<(NPAD + TB - 1) / TB, TB>>>();
    k_count<<<(EE + TB - 1) / TB, TB>>>(dst);
    k_scan<<<1, 1024>>>();
    k_place<<<(EE + TB - 1) / TB, TB>>>(src, dst);

    // layer-0 A fragments from x
    k_convA<<<(NPAD * 16 + TB - 1) / TB, TB>>>(x);

    const int douts[3] = {128, 128, 64};
    for (int L = 0; L < 3; L++) {
        int dout  = douts[L];
        int dout2 = 2 * dout;
        int last  = (L == 2);

        int bItems = (dout2 / 8) * 256;
        k_convB<<<(bItems + TB - 1) / TB, TB>>>(Wl[L], Wr[L], Ws[L], bl[L], bs[L], dout);

        dim3 gg(NTILES, dout2 / 128);
        k_mm<<<gg, 256>>>(dout);

        if (dout == 128) {
            k_agg<16, 128><<<(NN * 16 + TB - 1) / TB, TB>>>(
                (float*)d_out, last ? 1 : 0, last ? 0 : 1);
        } else {
            k_agg<8, 64><<<(NN * 8 + TB - 1) / TB, TB>>>(
                (float*)d_out, last ? 1 : 0, last ? 0 : 1);
        }
    }
}

// round 11
// speedup vs baseline: 2.0768x; 1.1043x over previous
#include <cuda_runtime.h>
#include <cuda_bf16.h>
#include <cuda_fp16.h>
#include <cstdint>

#define NN    50000
#define EE    800000
#define NPAD  50048
#define NTILES (NPAD / 128)          // 391 row-tiles of 128

// ---------------- scratch (device globals; no allocation allowed) -----------
__device__ __align__(16) __half g_Pv[(size_t)NPAD * 128];  // projected (gather), fp16
__device__ __align__(16) float  g_C [(size_t)NPAD * 128];  // self term, fp32
__device__ __align__(16) float  g_bias[128];               // bl + bs current layer
__device__ uint4 g_Ahi4[(size_t)NPAD * 16];                // A frags [r16][ks][lane]
__device__ uint4 g_Alo4[(size_t)NPAD * 16];
__device__ uint2 g_Bhi2[32 * 8 * 32];                      // B frags [ntile][ks][lane]
__device__ uint2 g_Blo2[32 * 8 * 32];
__device__ int g_deg[NPAD];
__device__ int g_rowoff[NPAD + 1];
__device__ int g_fill[NPAD];
__device__ int g_srcl[EE];

// ---------------- helpers ----------------------------------------------------
__device__ __forceinline__ void mma16816(float* c, const uint4& a, const uint2& b) {
    asm("mma.sync.aligned.m16n8k16.row.col.f32.bf16.bf16.f32 "
        "{%0,%1,%2,%3}, {%4,%5,%6,%7}, {%8,%9}, {%0,%1,%2,%3};"
        : "+f"(c[0]), "+f"(c[1]), "+f"(c[2]), "+f"(c[3])
        : "r"(a.x), "r"(a.y), "r"(a.z), "r"(a.w), "r"(b.x), "r"(b.y));
}

__device__ __forceinline__ void split2(float f0, float f1, uint32_t& hw, uint32_t& lw) {
    __nv_bfloat16 h0 = __float2bfloat16(f0);
    __nv_bfloat16 h1 = __float2bfloat16(f1);
    __nv_bfloat16 l0 = __float2bfloat16(f0 - __bfloat162float(h0));
    __nv_bfloat16 l1 = __float2bfloat16(f1 - __bfloat162float(h1));
    hw = (uint32_t)__bfloat16_as_ushort(h0) | ((uint32_t)__bfloat16_as_ushort(h1) << 16);
    lw = (uint32_t)__bfloat16_as_ushort(l0) | ((uint32_t)__bfloat16_as_ushort(l1) << 16);
}

// ---------------- CSR build --------------------------------------------------
__global__ void k_zero_deg() {
    int i = blockIdx.x * blockDim.x + threadIdx.x;
    if (i < NPAD) g_deg[i] = 0;
}
__global__ void k_count(const int* __restrict__ dst) {
    int e = blockIdx.x * blockDim.x + threadIdx.x;
    if (e < EE) atomicAdd(&g_deg[dst[e]], 1);
}
__global__ void __launch_bounds__(1024) k_scan() {
    __shared__ int ssum[1024];
    int t = threadIdx.x;
    const int CH = (NN + 1023) / 1024;
    int b0 = t * CH;
    int e0 = min(b0 + CH, NN);
    int s = 0;
    for (int i = b0; i < e0; i++) s += g_deg[i];
    ssum[t] = s;
    __syncthreads();
    for (int d = 1; d < 1024; d <<= 1) {
        int v = (t >= d) ? ssum[t - d] : 0;
        __syncthreads();
        ssum[t] += v;
        __syncthreads();
    }
    int run = ssum[t] - s;
    for (int i = b0; i < e0; i++) {
        g_rowoff[i] = run;
        g_fill[i]   = run;
        run += g_deg[i];
    }
    if (t == 1023) g_rowoff[NN] = run;
}
__global__ void k_place(const int* __restrict__ src, const int* __restrict__ dst) {
    int e = blockIdx.x * blockDim.x + threadIdx.x;
    if (e < EE) {
        int p = atomicAdd(&g_fill[dst[e]], 1);
        g_srcl[p] = src[e];
    }
}

// ---------------- convA: fp32 x[N,128] -> fragment-layout bf16 hi/lo --------
__global__ void __launch_bounds__(256)
k_convA(const float* __restrict__ A) {
    int idx = blockIdx.x * blockDim.x + threadIdx.x;
    if (idx >= NPAD * 16) return;
    int r16  = idx >> 8;
    int ks   = (idx >> 5) & 7;
    int lane = idx & 31;
    int r = r16 * 16 + (lane >> 2);
    int c = ks * 16 + (lane & 3) * 2;

    float2 p00 = (r     < NN) ? *(const float2*)(A + (size_t)r * 128 + c)
                              : make_float2(0.f, 0.f);
    float2 p10 = (r + 8 < NN) ? *(const float2*)(A + (size_t)(r + 8) * 128 + c)
                              : make_float2(0.f, 0.f);
    float2 p01 = (r     < NN) ? *(const float2*)(A + (size_t)r * 128 + c + 8)
                              : make_float2(0.f, 0.f);
    float2 p11 = (r + 8 < NN) ? *(const float2*)(A + (size_t)(r + 8) * 128 + c + 8)
                              : make_float2(0.f, 0.f);

    uint4 hv, lv;
    split2(p00.x, p00.y, hv.x, lv.x);
    split2(p10.x, p10.y, hv.y, lv.y);
    split2(p01.x, p01.y, hv.z, lv.z);
    split2(p11.x, p11.y, hv.w, lv.w);
    g_Ahi4[idx] = hv;
    g_Alo4[idx] = lv;
}

// ---------------- convB: fused [Wl | Wr+Ws] -> fragment hi/lo + bias --------
__global__ void __launch_bounds__(256)
k_convB(const float* __restrict__ Wl, const float* __restrict__ Wr,
        const float* __restrict__ Ws, const float* __restrict__ bl,
        const float* __restrict__ bs, int dout) {
    int dout2 = 2 * dout;
    int items = (dout2 / 8) * 256;
    int idx = blockIdx.x * blockDim.x + threadIdx.x;
    if (idx < items) {
        int ntile = idx >> 8;
        int ks    = (idx >> 5) & 7;
        int lane  = idx & 31;
        int n  = ntile * 8 + (lane >> 2);
        int k0 = ks * 16 + (lane & 3) * 2;

        float v[4];
#pragma unroll
        for (int i = 0; i < 4; i++) {
            int k = k0 + (i >> 1) * 8 + (i & 1);
            v[i] = (n < dout) ? Wl[k * dout + n]
                              : Wr[k * dout + (n - dout)] + Ws[k * dout + (n - dout)];
        }
        uint2 hv, lv;
        split2(v[0], v[1], hv.x, lv.x);
        split2(v[2], v[3], hv.y, lv.y);
        g_Bhi2[idx] = hv;
        g_Blo2[idx] = lv;
    }
    if (idx < dout) g_bias[idx] = bl[idx] + bs[idx];
}

// ---------------- HMMA GEMM -> P (fp16) and C (fp32) ------------------------
__global__ void __launch_bounds__(256)
k_mm(int dout) {
    int tid = threadIdx.x, wid = tid >> 5, lane = tid & 31;
    int wr = wid & 3, wc = wid >> 2;
    int tileRow = blockIdx.x, colB = blockIdx.y;
    int r16b = tileRow * 8 + wr * 2;
    int ntb  = colB * 16 + wc * 8;

    float acc[2][8][4];
#pragma unroll
    for (int m = 0; m < 2; m++)
#pragma unroll
        for (int j = 0; j < 8; j++)
#pragma unroll
            for (int q = 0; q < 4; q++) acc[m][j][q] = 0.f;

#pragma unroll
    for (int ks = 0; ks < 8; ks++) {
        uint4 ah0 = g_Ahi4[((size_t)(r16b + 0) * 8 + ks) * 32 + lane];
        uint4 ah1 = g_Ahi4[((size_t)(r16b + 1) * 8 + ks) * 32 + lane];
        uint4 al0 = g_Alo4[((size_t)(r16b + 0) * 8 + ks) * 32 + lane];
        uint4 al1 = g_Alo4[((size_t)(r16b + 1) * 8 + ks) * 32 + lane];
        uint2 bh[8], bl_[8];
#pragma unroll
        for (int j = 0; j < 8; j++) {
            bh[j]  = g_Bhi2[((ntb + j) * 8 + ks) * 32 + lane];
            bl_[j] = g_Blo2[((ntb + j) * 8 + ks) * 32 + lane];
        }
#pragma unroll
        for (int j = 0; j < 8; j++) {
            mma16816(acc[0][j], ah0, bh[j]);
            mma16816(acc[1][j], ah1, bh[j]);
            mma16816(acc[0][j], ah0, bl_[j]);
            mma16816(acc[1][j], ah1, bl_[j]);
            mma16816(acc[0][j], al0, bh[j]);
            mma16816(acc[1][j], al1, bh[j]);
        }
    }

#pragma unroll
    for (int m = 0; m < 2; m++) {
        int r = tileRow * 128 + wr * 32 + m * 16 + (lane >> 2);
#pragma unroll
        for (int j = 0; j < 8; j++) {
            int col = colB * 128 + wc * 64 + j * 8 + (lane & 3) * 2;
            if (col < dout) {
                *(__half2*)(g_Pv + (size_t)r * dout + col) =
                    __floats2half2_rn(acc[m][j][0], acc[m][j][1]);
                *(__half2*)(g_Pv + (size_t)(r + 8) * dout + col) =
                    __floats2half2_rn(acc[m][j][2], acc[m][j][3]);
            } else {
                int cc = col - dout;
                *(float2*)(g_C + (size_t)r * dout + cc) =
                    make_float2(acc[m][j][0], acc[m][j][1]);
                *(float2*)(g_C + (size_t)(r + 8) * dout + cc) =
                    make_float2(acc[m][j][2], acc[m][j][3]);
            }
        }
    }
}

// ---------------- fused aggregate + epilogue + fragment write ---------------
template <int CPR8, int DOUT>
__global__ void __launch_bounds__(256)
k_agg(float* __restrict__ out, int writeOut, int relu) {
    int gid  = blockIdx.x * blockDim.x + threadIdx.x;
    int node = gid / CPR8;
    int cidx = gid % CPR8;
    if (node >= NN) return;
    int c0  = cidx * 8;
    int beg = g_rowoff[node];
    int end = g_rowoff[node + 1];

    const uint4* P4 = (const uint4*)g_Pv;
    float acc[8];
#pragma unroll
    for (int i = 0; i < 8; i++) acc[i] = 0.f;

    int j = beg;
    // MLP-4 unrolled gather: 4 independent index loads, then 4 independent rows
    for (; j + 4 <= end; j += 4) {
        int s0 = __ldg(&g_srcl[j + 0]);
        int s1 = __ldg(&g_srcl[j + 1]);
        int s2 = __ldg(&g_srcl[j + 2]);
        int s3 = __ldg(&g_srcl[j + 3]);
        uint4 v0 = P4[(size_t)s0 * CPR8 + cidx];
        uint4 v1 = P4[(size_t)s1 * CPR8 + cidx];
        uint4 v2 = P4[(size_t)s2 * CPR8 + cidx];
        uint4 v3 = P4[(size_t)s3 * CPR8 + cidx];
        const uint4* vv[4] = {&v0, &v1, &v2, &v3};
#pragma unroll
        for (int u = 0; u < 4; u++) {
            uint32_t w[4] = {vv[u]->x, vv[u]->y, vv[u]->z, vv[u]->w};
#pragma unroll
            for (int q = 0; q < 4; q++) {
                float2 f = __half22float2(*(__half2*)&w[q]);
                acc[2 * q]     += f.x;
                acc[2 * q + 1] += f.y;
            }
        }
    }
    for (; j < end; j++) {
        int s = __ldg(&g_srcl[j]);
        uint4 v = P4[(size_t)s * CPR8 + cidx];
        uint32_t w[4] = {v.x, v.y, v.z, v.w};
#pragma unroll
        for (int q = 0; q < 4; q++) {
            float2 f = __half22float2(*(__half2*)&w[q]);
            acc[2 * q]     += f.x;
            acc[2 * q + 1] += f.y;
        }
    }
    float inv = 1.0f / fmaxf((float)(end - beg), 1.0f);

    float4 C0 = *(const float4*)(g_C + (size_t)node * DOUT + c0);
    float4 C1 = *(const float4*)(g_C + (size_t)node * DOUT + c0 + 4);
    float4 b0 = *(const float4*)(g_bias + c0);
    float4 b1 = *(const float4*)(g_bias + c0 + 4);
    float o[8];
    o[0] = acc[0] * inv + C0.x + b0.x;  o[1] = acc[1] * inv + C0.y + b0.y;
    o[2] = acc[2] * inv + C0.z + b0.z;  o[3] = acc[3] * inv + C0.w + b0.w;
    o[4] = acc[4] * inv + C1.x + b1.x;  o[5] = acc[5] * inv + C1.y + b1.y;
    o[6] = acc[6] * inv + C1.z + b1.z;  o[7] = acc[7] * inv + C1.w + b1.w;
    if (relu) {
#pragma unroll
        for (int i = 0; i < 8; i++) o[i] = fmaxf(o[i], 0.f);
    }

    if (writeOut) {
        *(float4*)(out + (size_t)node * DOUT + c0)     = make_float4(o[0], o[1], o[2], o[3]);
        *(float4*)(out + (size_t)node * DOUT + c0 + 4) = make_float4(o[4], o[5], o[6], o[7]);
    } else {
        // write bf16 hi/lo fragments for next layer's A (row=node, cols c0..c0+7)
        int r16  = node >> 4;
        int ks   = c0 >> 4;
        int word = (((c0 >> 3) & 1) << 1) | ((node >> 3) & 1);
        uint32_t* AH = (uint32_t*)g_Ahi4;
        uint32_t* AL = (uint32_t*)g_Alo4;
        size_t base = ((size_t)r16 * 256 + (size_t)ks * 32) * 4;
#pragma unroll
        for (int p = 0; p < 4; p++) {
            int lane = ((node & 7) << 2) | p;
            uint32_t hw, lw;
            split2(o[2 * p], o[2 * p + 1], hw, lw);
            AH[base + lane * 4 + word] = hw;
            AL[base + lane * 4 + word] = lw;
        }
    }
}

// ---------------- launch ----------------------------------------------------
static cudaStream_t g_s2;
static cudaEvent_t  g_evFork, g_evJoin;
static bool g_init = false;

extern "C" void kernel_launch(void* const* d_in, const int* in_sizes, int n_in,
                              void* d_out, int out_size) {
    if (!g_init) {
        cudaStreamCreateWithFlags(&g_s2, cudaStreamNonBlocking);
        cudaEventCreateWithFlags(&g_evFork, cudaEventDisableTiming);
        cudaEventCreateWithFlags(&g_evJoin, cudaEventDisableTiming);
        g_init = true;
    }

    const float* x   = (const float*)d_in[0];
    const int*   ei  = (const int*)d_in[1];   // JAX x64 disabled -> int32
    const int*   src = ei;
    const int*   dst = ei + EE;

    const float* Wl[3] = {(const float*)d_in[4],  (const float*)d_in[9],  (const float*)d_in[14]};
    const float* bl[3] = {(const float*)d_in[5],  (const float*)d_in[10], (const float*)d_in[15]};
    const float* Wr[3] = {(const float*)d_in[6],  (const float*)d_in[11], (const float*)d_in[16]};
    const float* Ws[3] = {(const float*)d_in[7],  (const float*)d_in[12], (const float*)d_in[17]};
    const float* bs[3] = {(const float*)d_in[8],  (const float*)d_in[13], (const float*)d_in[18]};

    const int TB = 256;

    // ---- fork: CSR build on side stream, overlapped with L0 conv + GEMM ----
    cudaEventRecord(g_evFork, 0);
    cudaStreamWaitEvent(g_s2, g_evFork, 0);
    k_zero_deg<<<(NPAD + TB - 1) / TB, TB, 0, g_s2>>>();
    k_count<<<(EE + TB - 1) / TB, TB, 0, g_s2>>>(dst);
    k_scan<<<1, 1024, 0, g_s2>>>();
    k_place<<<(EE + TB - 1) / TB, TB, 0, g_s2>>>(src, dst);
    cudaEventRecord(g_evJoin, g_s2);

    // ---- main chain on the capture (legacy) stream ----
    k_convA<<<(NPAD * 16 + TB - 1) / TB, TB>>>(x);

    const int douts[3] = {128, 128, 64};
    for (int L = 0; L < 3; L++) {
        int dout  = douts[L];
        int dout2 = 2 * dout;
        int last  = (L == 2);

        int bItems = (dout2 / 8) * 256;
        k_convB<<<(bItems + TB - 1) / TB, TB>>>(Wl[L], Wr[L], Ws[L], bl[L], bs[L], dout);

        dim3 gg(NTILES, dout2 / 128);
        k_mm<<<gg, 256>>>(dout);

        if (L == 0) cudaStreamWaitEvent(0, g_evJoin, 0);  // join before first agg

        if (dout == 128) {
            k_agg<16, 128><<<(NN * 16 + TB - 1) / TB, TB>>>(
                (float*)d_out, last ? 1 : 0, last ? 0 : 1);
        } else {
            k_agg<8, 64><<<(NN * 8 + TB - 1) / TB, TB>>>(
                (float*)d_out, last ? 1 : 0, last ? 0 : 1);
        }
    }
}